// round 12
// baseline (speedup 1.0000x reference)
#include <cuda_runtime.h>
#include <cuda_bf16.h>
#include <cstdint>

#define M_DIM 4096
#define N_DIM 8192
#define K_DIM 2048
#define K2    4096            // [hi | lo] along K

// GEMM tiling: 8 warps, 2(m) x 4(n), warp tile 64x32, 2 CTAs/SM
#define BM 128
#define BN 128
#define BK 32
#define NSTAGE 3
#define KT_TILES (K_DIM / BK)   // 64
#define NTHREADS 256
#define NWARPS 8

// smem: mbarriers at [0,48), tiles from 1024; 64B rows w/ XOR swizzle
#define ROW64     64
#define MB_FULL   0           // full[s] = 0 + s*8
#define MB_EMPTY  24          // empty[s] = 24 + s*8
#define SM_TILE   1024
#define AHI_OFF   0
#define ALO_OFF   8192
#define BHI_OFF   16384
#define BLO_OFF   24576
#define STAGE_B   32768
#define SMEM_TOTAL (SM_TILE + NSTAGE * STAGE_B)   // 99328/CTA (2 CTAs/SM)

// ---------------------------------------------------------------------------
// device scratch (allocation-free)
// ---------------------------------------------------------------------------
__device__ __nv_bfloat16 g_A2[(size_t)M_DIM * K2];   // [M, 2K]: hi | lo
__device__ __nv_bfloat16 g_B2[(size_t)N_DIM * K2];   // [N, 2K]: hi | lo
__device__ float g_scratch[(size_t)M_DIM * N_DIM];
__device__ unsigned g_rowmax_u[M_DIM];

// ---------------------------------------------------------------------------
// helpers
// ---------------------------------------------------------------------------
__device__ __forceinline__ uint32_t smem_u32(const void* p) {
    uint32_t a;
    asm("{ .reg .u64 t; cvta.to.shared.u64 t, %1; cvt.u32.u64 %0, t; }" : "=r"(a) : "l"(p));
    return a;
}

#define CP_ASYNC16(smem_addr, gptr) \
    asm volatile("cp.async.cg.shared.global [%0], [%1], 16;" :: "r"(smem_addr), "l"(gptr))

#define MBARRIER_INIT(addr, cnt) \
    asm volatile("mbarrier.init.shared.b64 [%0], %1;" :: "r"((uint32_t)(addr)), "r"((uint32_t)(cnt)) : "memory")
#define MBARRIER_ARRIVE(addr) \
    asm volatile("mbarrier.arrive.shared.b64 _, [%0];" :: "r"((uint32_t)(addr)) : "memory")
// .noinc is load-bearing: arrivals count against the init() count instead of
// first incrementing the pending count (which deadlocks a fixed-count barrier).
#define CP_ASYNC_MBAR_ARRIVE(addr) \
    asm volatile("cp.async.mbarrier.arrive.noinc.shared::cta.b64 [%0];" :: "r"((uint32_t)(addr)) : "memory")

#define MBARRIER_WAIT_PARITY(mbar_smem_addr, phase_parity) do { \
    uint32_t _mbar = (uint32_t)(mbar_smem_addr); \
    uint32_t _parity = (uint32_t)(phase_parity); \
    uint32_t _done; \
    asm volatile( \
        "{\n\t.reg .pred p;\n\t" \
        "mbarrier.try_wait.parity.acquire.cta.shared::cta.b64 p, [%1], %2;\n\t" \
        "selp.b32 %0, 1, 0, p;\n\t}" \
        : "=r"(_done) : "r"(_mbar), "r"(_parity) : "memory"); \
    if (!_done) { \
        asm volatile( \
            "{\n\t.reg .pred P1;\n\t" \
            "WAIT_LOOP_%=:\n\t" \
            "mbarrier.try_wait.parity.acquire.cta.shared::cta.b64 P1, [%0], %1, 0x989680;\n\t" \
            "@P1 bra.uni WAIT_DONE_%=;\n\t" \
            "bra.uni WAIT_LOOP_%=;\n\t" \
            "WAIT_DONE_%=:\n\t}" \
            :: "r"(_mbar), "r"(_parity) : "memory"); \
    } \
} while(0)

__device__ __forceinline__ void ldsm_x4(uint32_t* r, uint32_t addr) {
    asm volatile("ldmatrix.sync.aligned.m8n8.x4.shared.b16 {%0,%1,%2,%3}, [%4];"
                 : "=r"(r[0]), "=r"(r[1]), "=r"(r[2]), "=r"(r[3]) : "r"(addr));
}

__device__ __forceinline__ void mma16816(float* d, const uint32_t* a, const uint32_t* b) {
    asm volatile(
        "mma.sync.aligned.m16n8k16.row.col.f32.bf16.bf16.f32 "
        "{%0,%1,%2,%3}, {%4,%5,%6,%7}, {%8,%9}, {%0,%1,%2,%3};"
        : "+f"(d[0]), "+f"(d[1]), "+f"(d[2]), "+f"(d[3])
        : "r"(a[0]), "r"(a[1]), "r"(a[2]), "r"(a[3]), "r"(b[0]), "r"(b[1]));
}

// swizzled smem byte offset for 16B chunk c of row r (64B rows)
__device__ __forceinline__ uint32_t swz(uint32_t row, uint32_t c) {
    return row * ROW64 + ((c ^ ((row >> 1) & 3)) << 4);
}

// order-preserving float<->uint for atomicMax-based rowmax
__device__ __forceinline__ unsigned f2ord(float x) {
    unsigned u = __float_as_uint(x);
    return (u & 0x80000000u) ? ~u : (u | 0x80000000u);
}
__device__ __forceinline__ float ord2f(unsigned u) {
    u = (u & 0x80000000u) ? (u ^ 0x80000000u) : ~u;
    return __uint_as_float(u);
}

// ---------------------------------------------------------------------------
// fused prep: split x and w to bf16 [hi|lo], init rowmax
// grid: blocks [0, NA) -> A, [NA, NA+NB) -> B;  rmax init folded into block 0..15
// ---------------------------------------------------------------------------
#define NA_BLOCKS ((M_DIM * (K_DIM / 4)) / 256)   // 8192
#define NB_BLOCKS ((N_DIM * (K_DIM / 4)) / 256)   // 16384

__global__ __launch_bounds__(256)
void prep_kernel(const float* __restrict__ x, const float* __restrict__ w,
                 __nv_bfloat16* __restrict__ a2, __nv_bfloat16* __restrict__ b2,
                 unsigned* __restrict__ rmax) {
    const int bid = blockIdx.x;
    const float* src = (bid < NA_BLOCKS) ? x : w;
    __nv_bfloat16* dst = (bid < NA_BLOCKS) ? a2 : b2;
    const size_t i = (size_t)(bid < NA_BLOCKS ? bid : bid - NA_BLOCKS) * 256 + threadIdx.x;

    if (bid < 16) {   // 16*256 = 4096 rowmax entries
        rmax[bid * 256 + threadIdx.x] = 0u;
    }

    float4 v = reinterpret_cast<const float4*>(src)[i];
    size_t r = i >> 9;          // / (2048/4)
    size_t k4 = (i & 511) * 4;
    float f[4] = {v.x, v.y, v.z, v.w};
    __nv_bfloat16 h[4], l[4];
#pragma unroll
    for (int j = 0; j < 4; j++) {
        h[j] = __float2bfloat16(f[j]);
        l[j] = __float2bfloat16(f[j] - __bfloat162float(h[j]));
    }
    __nv_bfloat162* dh = reinterpret_cast<__nv_bfloat162*>(dst + r * K2 + k4);
    __nv_bfloat162* dl = reinterpret_cast<__nv_bfloat162*>(dst + r * K2 + K_DIM + k4);
    dh[0] = __nv_bfloat162{h[0], h[1]};
    dh[1] = __nv_bfloat162{h[2], h[3]};
    dl[0] = __nv_bfloat162{l[0], l[1]};
    dl[1] = __nv_bfloat162{l[2], l[3]};
}

// ---------------------------------------------------------------------------
// bf16 split-GEMM via mma.sync, mbarrier self-paced pipeline, 2 CTAs/SM,
// early stage-release + mid-iteration prefetch, fused rowmax
// C[M,N] = Ahi*Bhi^T + Alo*Bhi^T + Ahi*Blo^T
// ---------------------------------------------------------------------------
__global__ __launch_bounds__(NTHREADS, 2)
void hgemm_kernel(const __nv_bfloat16* __restrict__ A,
                  const __nv_bfloat16* __restrict__ B,
                  float* __restrict__ C,
                  unsigned* __restrict__ rmax) {
    extern __shared__ __align__(128) char smem[];
    const uint32_t sb = smem_u32(smem);
    const int tid = threadIdx.x;
    const int wid = tid >> 5;
    const int lid = tid & 31;
    const int warp_m = wid & 1;      // 2 warps along M (64 rows each)
    const int warp_n = wid >> 1;     // 4 warps along N (32 cols each)

    // grouped raster: 32 m-tiles x 64 n-tiles, GROUP_M = 8
    const int num_n = N_DIM / BN;                 // 64
    const int pid = blockIdx.x;
    const int grp = pid / (8 * num_n);
    const int pm = grp * 8 + (pid & 7);
    const int pn = (pid % (8 * num_n)) >> 3;
    const int bm = pm * BM;
    const int bn = pn * BN;

    // mbarrier init
    if (tid == 0) {
#pragma unroll
        for (int s = 0; s < NSTAGE; s++) {
            MBARRIER_INIT(sb + MB_FULL + s * 8, NTHREADS);
            MBARRIER_INIT(sb + MB_EMPTY + s * 8, NWARPS);
        }
    }
    __syncthreads();

    // gmem load mapping: 256 threads; row = tid>>1 (0..127), 2 chunks each
    const int r0 = tid >> 1;
    const int cp0 = (tid & 1) * 2;   // chunks cp0, cp0+1
    const __nv_bfloat16* gA = A + (size_t)(bm + r0) * K2 + cp0 * 8;
    const __nv_bfloat16* gB = B + (size_t)(bn + r0) * K2 + cp0 * 8;
    const uint32_t d0 = swz((uint32_t)r0, (uint32_t)cp0);
    const uint32_t d1 = swz((uint32_t)r0, (uint32_t)cp0 + 1);

    auto load_stage = [&](int s, int kt) {
        uint32_t st = sb + SM_TILE + s * STAGE_B;
        const int kc = kt * BK;
        const __nv_bfloat16* a = gA + kc;
        const __nv_bfloat16* b = gB + kc;
        CP_ASYNC16(st + AHI_OFF + d0, a);
        CP_ASYNC16(st + AHI_OFF + d1, a + 8);
        CP_ASYNC16(st + ALO_OFF + d0, a + K_DIM);
        CP_ASYNC16(st + ALO_OFF + d1, a + K_DIM + 8);
        CP_ASYNC16(st + BHI_OFF + d0, b);
        CP_ASYNC16(st + BHI_OFF + d1, b + 8);
        CP_ASYNC16(st + BLO_OFF + d0, b + K_DIM);
        CP_ASYNC16(st + BLO_OFF + d1, b + K_DIM + 8);
        CP_ASYNC_MBAR_ARRIVE(sb + MB_FULL + s * 8);
    };

    float acc[4][4][4];
#pragma unroll
    for (int i = 0; i < 4; i++)
#pragma unroll
        for (int j = 0; j < 4; j++)
#pragma unroll
            for (int q = 0; q < 4; q++)
                acc[i][j][q] = 0.0f;

    // prologue: fill stages 0 and 1 (no empty-wait on first use)
    load_stage(0, 0);
    load_stage(1, 1);

    // ldmatrix lane addressing (row + chunk index per lane)
    const int a_row = warp_m * 64 + (lid & 15);                         // + i*16
    const int a_ch  = (lid >> 4);                                       // + ks*2
    const int b_row = warp_n * 32 + (lid & 7) + ((lid >> 4) & 1) * 8;   // + j*16
    const int b_ch  = ((lid >> 3) & 1);                                 // + ks*2

    for (int kt = 0; kt < KT_TILES; kt++) {
        const int cs = kt % NSTAGE;
        // consume: wait stage full (parity = (kt/3)&1)
        MBARRIER_WAIT_PARITY(sb + MB_FULL + cs * 8, (uint32_t)((kt / NSTAGE) & 1));

        const uint32_t st = sb + SM_TILE + cs * STAGE_B;
        uint32_t ah[4][4], al[4][4], bh[8], bl[8];

        // ---- ks = 0: ldsm ----
#pragma unroll
        for (int i = 0; i < 4; i++) {
            uint32_t rb = swz((uint32_t)(a_row + i * 16), (uint32_t)a_ch);
            ldsm_x4(ah[i], st + AHI_OFF + rb);
            ldsm_x4(al[i], st + ALO_OFF + rb);
        }
#pragma unroll
        for (int j = 0; j < 2; j++) {
            uint32_t rb = swz((uint32_t)(b_row + j * 16), (uint32_t)b_ch);
            ldsm_x4(bh + j * 4, st + BHI_OFF + rb);
            ldsm_x4(bl + j * 4, st + BLO_OFF + rb);
        }

        // ---- mid-iteration prefetch of kt+2 (separate stage buffer) ----
        {
            const int nk = kt + 2;
            if (nk < KT_TILES) {
                const int ps = nk % NSTAGE;
                if (nk >= NSTAGE)
                    MBARRIER_WAIT_PARITY(sb + MB_EMPTY + ps * 8,
                                         (uint32_t)(((nk / NSTAGE) - 1) & 1));
                load_stage(ps, nk);
            }
        }

        // ---- ks = 0: mma ----
#pragma unroll
        for (int i = 0; i < 4; i++)
#pragma unroll
            for (int jj = 0; jj < 4; jj++)
                mma16816(acc[i][jj], ah[i], bh + jj * 2);   // hi*hi
#pragma unroll
        for (int i = 0; i < 4; i++)
#pragma unroll
            for (int jj = 0; jj < 4; jj++)
                mma16816(acc[i][jj], al[i], bh + jj * 2);   // lo*hi
#pragma unroll
        for (int i = 0; i < 4; i++)
#pragma unroll
            for (int jj = 0; jj < 4; jj++)
                mma16816(acc[i][jj], ah[i], bl + jj * 2);   // hi*lo

        // ---- ks = 1: ldsm ----
#pragma unroll
        for (int i = 0; i < 4; i++) {
            uint32_t rb = swz((uint32_t)(a_row + i * 16), (uint32_t)(2 + a_ch));
            ldsm_x4(ah[i], st + AHI_OFF + rb);
            ldsm_x4(al[i], st + ALO_OFF + rb);
        }
#pragma unroll
        for (int j = 0; j < 2; j++) {
            uint32_t rb = swz((uint32_t)(b_row + j * 16), (uint32_t)(2 + b_ch));
            ldsm_x4(bh + j * 4, st + BHI_OFF + rb);
            ldsm_x4(bl + j * 4, st + BLO_OFF + rb);
        }
        // all smem reads of this stage done (data in regs) -> release stage now
        __syncwarp();
        if (lid == 0) MBARRIER_ARRIVE(sb + MB_EMPTY + cs * 8);

        // ---- ks = 1: mma ----
#pragma unroll
        for (int i = 0; i < 4; i++)
#pragma unroll
            for (int jj = 0; jj < 4; jj++)
                mma16816(acc[i][jj], ah[i], bh + jj * 2);   // hi*hi
#pragma unroll
        for (int i = 0; i < 4; i++)
#pragma unroll
            for (int jj = 0; jj < 4; jj++)
                mma16816(acc[i][jj], al[i], bh + jj * 2);   // lo*hi
#pragma unroll
        for (int i = 0; i < 4; i++)
#pragma unroll
            for (int jj = 0; jj < 4; jj++)
                mma16816(acc[i][jj], ah[i], bl + jj * 2);   // hi*lo
    }

    // epilogue: store C + fused row-max atomics (per-warp independent)
    const int erow = bm + warp_m * 64 + (lid >> 2);
    const int ecol = bn + warp_n * 32 + (lid & 3) * 2;
#pragma unroll
    for (int i = 0; i < 4; i++) {
#pragma unroll
        for (int half = 0; half < 2; half++) {
            float m = -3.402823466e+38f;
#pragma unroll
            for (int jj = 0; jj < 4; jj++) {
                float v0 = acc[i][jj][half * 2 + 0];
                float v1 = acc[i][jj][half * 2 + 1];
                float* p = C + (size_t)(erow + i * 16 + half * 8) * N_DIM + ecol + jj * 8;
                *reinterpret_cast<float2*>(p) = make_float2(v0, v1);
                m = fmaxf(m, fmaxf(v0, v1));
            }
            m = fmaxf(m, __shfl_xor_sync(0xffffffffu, m, 1));
            m = fmaxf(m, __shfl_xor_sync(0xffffffffu, m, 2));
            if ((lid & 3) == 0)
                atomicMax(&rmax[erow + i * 16 + half * 8], f2ord(m));
        }
    }
}

// ---------------------------------------------------------------------------
// gelu epilogue
// ---------------------------------------------------------------------------
__device__ __forceinline__ float gelu_tanh(float x) {
    const float c0 = 0.7978845608028654f;
    const float c1 = 0.044715f;
    float inner = c0 * fmaf(c1 * x, x * x, x);
    return 0.5f * x * (1.0f + tanhf(inner));
}

__global__ __launch_bounds__(256)
void gelu_kernel(const float* __restrict__ C, const unsigned* __restrict__ rmax,
                 float* __restrict__ out) {
    const size_t base = (size_t)blockIdx.x * 4096;
    const int row = (int)(base / N_DIM);
    const float mx = ord2f(rmax[row]);
    const float4* c4 = reinterpret_cast<const float4*>(C + base);
    float4* o4 = reinterpret_cast<float4*>(out + base);
    const int tid = threadIdx.x;
#pragma unroll
    for (int it = 0; it < 4; it++) {
        float4 v = c4[tid + it * 256];
        float4 r;
        r.x = gelu_tanh(v.x - mx);
        r.y = gelu_tanh(v.y - mx);
        r.z = gelu_tanh(v.z - mx);
        r.w = gelu_tanh(v.w - mx);
        o4[tid + it * 256] = r;
    }
}

// ---------------------------------------------------------------------------
extern "C" void kernel_launch(void* const* d_in, const int* in_sizes, int n_in,
                              void* d_out, int out_size) {
    const float* x = (const float*)d_in[0];   // [M, K]
    const float* w = (const float*)d_in[1];   // [N, K]
    float* out = (float*)d_out;               // [M, N]

    void *a2, *b2, *scratch, *rowmax;
    cudaGetSymbolAddress(&a2, g_A2);
    cudaGetSymbolAddress(&b2, g_B2);
    cudaGetSymbolAddress(&scratch, g_scratch);
    cudaGetSymbolAddress(&rowmax, g_rowmax_u);

    prep_kernel<<<NA_BLOCKS + NB_BLOCKS, 256>>>(
        x, w, (__nv_bfloat16*)a2, (__nv_bfloat16*)b2, (unsigned*)rowmax);

    cudaFuncSetAttribute(hgemm_kernel, cudaFuncAttributeMaxDynamicSharedMemorySize, SMEM_TOTAL);
    hgemm_kernel<<<(M_DIM / BM) * (N_DIM / BN), NTHREADS, SMEM_TOTAL>>>(
        (const __nv_bfloat16*)a2, (const __nv_bfloat16*)b2,
        (float*)scratch, (unsigned*)rowmax);

    gelu_kernel<<<(size_t)M_DIM * N_DIM / 4096, 256>>>(
        (float*)scratch, (unsigned*)rowmax, out);
}

// round 13
// speedup vs baseline: 1.0885x; 1.0885x over previous
#include <cuda_runtime.h>
#include <cuda_bf16.h>
#include <cstdint>

#define M_DIM 4096
#define N_DIM 8192
#define K_DIM 2048
#define K2    4096            // [hi | lo] along K

// GEMM tiling: 8 warps, 2(m) x 4(n), warp tile 64x32, 2 CTAs/SM
#define BM 128
#define BN 128
#define BK 32
#define NSTAGE 3
#define KT_TILES (K_DIM / BK)   // 64
#define NTHREADS 256
#define NWARPS 8

// smem: mbarriers at [0,48), tiles from 1024; 64B rows w/ XOR swizzle
#define ROW64     64
#define MB_FULL   0           // full[s] = 0 + s*8
#define MB_EMPTY  24          // empty[s] = 24 + s*8
#define SM_TILE   1024
#define AHI_OFF   0
#define ALO_OFF   8192
#define BHI_OFF   16384
#define BLO_OFF   24576
#define STAGE_B   32768
#define SMEM_TOTAL (SM_TILE + NSTAGE * STAGE_B)   // 99328/CTA (2 CTAs/SM)

// ---------------------------------------------------------------------------
// device scratch (allocation-free)
// ---------------------------------------------------------------------------
__device__ __nv_bfloat16 g_A2[(size_t)M_DIM * K2];   // [M, 2K]: hi | lo
__device__ __nv_bfloat16 g_B2[(size_t)N_DIM * K2];   // [N, 2K]: hi | lo
__device__ float g_scratch[(size_t)M_DIM * N_DIM];
__device__ unsigned g_rowmax_u[M_DIM];

// ---------------------------------------------------------------------------
// helpers
// ---------------------------------------------------------------------------
__device__ __forceinline__ uint32_t smem_u32(const void* p) {
    uint32_t a;
    asm("{ .reg .u64 t; cvta.to.shared.u64 t, %1; cvt.u32.u64 %0, t; }" : "=r"(a) : "l"(p));
    return a;
}

#define CP_ASYNC16(smem_addr, gptr) \
    asm volatile("cp.async.cg.shared.global [%0], [%1], 16;" :: "r"(smem_addr), "l"(gptr))

#define MBARRIER_INIT(addr, cnt) \
    asm volatile("mbarrier.init.shared.b64 [%0], %1;" :: "r"((uint32_t)(addr)), "r"((uint32_t)(cnt)) : "memory")
#define MBARRIER_ARRIVE(addr) \
    asm volatile("mbarrier.arrive.shared.b64 _, [%0];" :: "r"((uint32_t)(addr)) : "memory")
// .noinc is load-bearing: arrivals count against the init() count instead of
// first incrementing the pending count (which deadlocks a fixed-count barrier).
#define CP_ASYNC_MBAR_ARRIVE(addr) \
    asm volatile("cp.async.mbarrier.arrive.noinc.shared::cta.b64 [%0];" :: "r"((uint32_t)(addr)) : "memory")

#define MBARRIER_WAIT_PARITY(mbar_smem_addr, phase_parity) do { \
    uint32_t _mbar = (uint32_t)(mbar_smem_addr); \
    uint32_t _parity = (uint32_t)(phase_parity); \
    uint32_t _done; \
    asm volatile( \
        "{\n\t.reg .pred p;\n\t" \
        "mbarrier.try_wait.parity.acquire.cta.shared::cta.b64 p, [%1], %2;\n\t" \
        "selp.b32 %0, 1, 0, p;\n\t}" \
        : "=r"(_done) : "r"(_mbar), "r"(_parity) : "memory"); \
    if (!_done) { \
        asm volatile( \
            "{\n\t.reg .pred P1;\n\t" \
            "WAIT_LOOP_%=:\n\t" \
            "mbarrier.try_wait.parity.acquire.cta.shared::cta.b64 P1, [%0], %1, 0x989680;\n\t" \
            "@P1 bra.uni WAIT_DONE_%=;\n\t" \
            "bra.uni WAIT_LOOP_%=;\n\t" \
            "WAIT_DONE_%=:\n\t}" \
            :: "r"(_mbar), "r"(_parity) : "memory"); \
    } \
} while(0)

__device__ __forceinline__ void ldsm_x4(uint32_t* r, uint32_t addr) {
    asm volatile("ldmatrix.sync.aligned.m8n8.x4.shared.b16 {%0,%1,%2,%3}, [%4];"
                 : "=r"(r[0]), "=r"(r[1]), "=r"(r[2]), "=r"(r[3]) : "r"(addr));
}

__device__ __forceinline__ void mma16816(float* d, const uint32_t* a, const uint32_t* b) {
    asm volatile(
        "mma.sync.aligned.m16n8k16.row.col.f32.bf16.bf16.f32 "
        "{%0,%1,%2,%3}, {%4,%5,%6,%7}, {%8,%9}, {%0,%1,%2,%3};"
        : "+f"(d[0]), "+f"(d[1]), "+f"(d[2]), "+f"(d[3])
        : "r"(a[0]), "r"(a[1]), "r"(a[2]), "r"(a[3]), "r"(b[0]), "r"(b[1]));
}

// swizzled smem byte offset for 16B chunk c of row r (64B rows)
__device__ __forceinline__ uint32_t swz(uint32_t row, uint32_t c) {
    return row * ROW64 + ((c ^ ((row >> 1) & 3)) << 4);
}

// order-preserving float<->uint for atomicMax-based rowmax
__device__ __forceinline__ unsigned f2ord(float x) {
    unsigned u = __float_as_uint(x);
    return (u & 0x80000000u) ? ~u : (u | 0x80000000u);
}
__device__ __forceinline__ float ord2f(unsigned u) {
    u = (u & 0x80000000u) ? (u ^ 0x80000000u) : ~u;
    return __uint_as_float(u);
}

// ---------------------------------------------------------------------------
// fused prep: split x and w to bf16 [hi|lo], init rowmax
// ---------------------------------------------------------------------------
#define NA_BLOCKS ((M_DIM * (K_DIM / 4)) / 256)   // 8192
#define NB_BLOCKS ((N_DIM * (K_DIM / 4)) / 256)   // 16384

__global__ __launch_bounds__(256)
void prep_kernel(const float* __restrict__ x, const float* __restrict__ w,
                 __nv_bfloat16* __restrict__ a2, __nv_bfloat16* __restrict__ b2,
                 unsigned* __restrict__ rmax) {
    const int bid = blockIdx.x;
    const float* src = (bid < NA_BLOCKS) ? x : w;
    __nv_bfloat16* dst = (bid < NA_BLOCKS) ? a2 : b2;
    const size_t i = (size_t)(bid < NA_BLOCKS ? bid : bid - NA_BLOCKS) * 256 + threadIdx.x;

    if (bid < 16) {   // 16*256 = 4096 rowmax entries
        rmax[bid * 256 + threadIdx.x] = 0u;
    }

    float4 v = reinterpret_cast<const float4*>(src)[i];
    size_t r = i >> 9;          // / (2048/4)
    size_t k4 = (i & 511) * 4;
    float f[4] = {v.x, v.y, v.z, v.w};
    __nv_bfloat16 h[4], l[4];
#pragma unroll
    for (int j = 0; j < 4; j++) {
        h[j] = __float2bfloat16(f[j]);
        l[j] = __float2bfloat16(f[j] - __bfloat162float(h[j]));
    }
    __nv_bfloat162* dh = reinterpret_cast<__nv_bfloat162*>(dst + r * K2 + k4);
    __nv_bfloat162* dl = reinterpret_cast<__nv_bfloat162*>(dst + r * K2 + K_DIM + k4);
    dh[0] = __nv_bfloat162{h[0], h[1]};
    dh[1] = __nv_bfloat162{h[2], h[3]};
    dl[0] = __nv_bfloat162{l[0], l[1]};
    dl[1] = __nv_bfloat162{l[2], l[3]};
}

// ---------------------------------------------------------------------------
// bf16 split-GEMM via mma.sync, mbarrier self-paced pipeline (R11 ordering:
// end-of-iteration prefetch), early stage-release after ks=1 ldsm,
// 2 CTAs/SM, fused rowmax
// C[M,N] = Ahi*Bhi^T + Alo*Bhi^T + Ahi*Blo^T
// ---------------------------------------------------------------------------
__global__ __launch_bounds__(NTHREADS, 2)
void hgemm_kernel(const __nv_bfloat16* __restrict__ A,
                  const __nv_bfloat16* __restrict__ B,
                  float* __restrict__ C,
                  unsigned* __restrict__ rmax) {
    extern __shared__ __align__(128) char smem[];
    const uint32_t sb = smem_u32(smem);
    const int tid = threadIdx.x;
    const int wid = tid >> 5;
    const int lid = tid & 31;
    const int warp_m = wid & 1;      // 2 warps along M (64 rows each)
    const int warp_n = wid >> 1;     // 4 warps along N (32 cols each)

    // grouped raster: 32 m-tiles x 64 n-tiles, GROUP_M = 8
    const int num_n = N_DIM / BN;                 // 64
    const int pid = blockIdx.x;
    const int grp = pid / (8 * num_n);
    const int pm = grp * 8 + (pid & 7);
    const int pn = (pid % (8 * num_n)) >> 3;
    const int bm = pm * BM;
    const int bn = pn * BN;

    // mbarrier init
    if (tid == 0) {
#pragma unroll
        for (int s = 0; s < NSTAGE; s++) {
            MBARRIER_INIT(sb + MB_FULL + s * 8, NTHREADS);
            MBARRIER_INIT(sb + MB_EMPTY + s * 8, NWARPS);
        }
    }
    __syncthreads();

    // gmem load mapping: 256 threads; row = tid>>1 (0..127), 2 chunks each
    const int r0 = tid >> 1;
    const int cp0 = (tid & 1) * 2;   // chunks cp0, cp0+1
    const __nv_bfloat16* gA = A + (size_t)(bm + r0) * K2 + cp0 * 8;
    const __nv_bfloat16* gB = B + (size_t)(bn + r0) * K2 + cp0 * 8;
    const uint32_t d0 = swz((uint32_t)r0, (uint32_t)cp0);
    const uint32_t d1 = swz((uint32_t)r0, (uint32_t)cp0 + 1);

    auto load_stage = [&](int s, int kt) {
        uint32_t st = sb + SM_TILE + s * STAGE_B;
        const int kc = kt * BK;
        const __nv_bfloat16* a = gA + kc;
        const __nv_bfloat16* b = gB + kc;
        CP_ASYNC16(st + AHI_OFF + d0, a);
        CP_ASYNC16(st + AHI_OFF + d1, a + 8);
        CP_ASYNC16(st + ALO_OFF + d0, a + K_DIM);
        CP_ASYNC16(st + ALO_OFF + d1, a + K_DIM + 8);
        CP_ASYNC16(st + BHI_OFF + d0, b);
        CP_ASYNC16(st + BHI_OFF + d1, b + 8);
        CP_ASYNC16(st + BLO_OFF + d0, b + K_DIM);
        CP_ASYNC16(st + BLO_OFF + d1, b + K_DIM + 8);
        CP_ASYNC_MBAR_ARRIVE(sb + MB_FULL + s * 8);
    };

    float acc[4][4][4];
#pragma unroll
    for (int i = 0; i < 4; i++)
#pragma unroll
        for (int j = 0; j < 4; j++)
#pragma unroll
            for (int q = 0; q < 4; q++)
                acc[i][j][q] = 0.0f;

    // prologue: fill stages 0 and 1 (no empty-wait on first use)
    load_stage(0, 0);
    load_stage(1, 1);

    // ldmatrix lane addressing (row + chunk index per lane)
    const int a_row = warp_m * 64 + (lid & 15);                         // + i*16
    const int a_ch  = (lid >> 4);                                       // + ks*2
    const int b_row = warp_n * 32 + (lid & 7) + ((lid >> 4) & 1) * 8;   // + j*16
    const int b_ch  = ((lid >> 3) & 1);                                 // + ks*2

    for (int kt = 0; kt < KT_TILES; kt++) {
        const int cs = kt % NSTAGE;
        // consume: wait stage full (parity = (kt/3)&1)
        MBARRIER_WAIT_PARITY(sb + MB_FULL + cs * 8, (uint32_t)((kt / NSTAGE) & 1));

        const uint32_t st = sb + SM_TILE + cs * STAGE_B;
        uint32_t ah[4][4], al[4][4], bh[8], bl[8];

        // ---- ks = 0: ldsm ----
#pragma unroll
        for (int i = 0; i < 4; i++) {
            uint32_t rb = swz((uint32_t)(a_row + i * 16), (uint32_t)a_ch);
            ldsm_x4(ah[i], st + AHI_OFF + rb);
            ldsm_x4(al[i], st + ALO_OFF + rb);
        }
#pragma unroll
        for (int j = 0; j < 2; j++) {
            uint32_t rb = swz((uint32_t)(b_row + j * 16), (uint32_t)b_ch);
            ldsm_x4(bh + j * 4, st + BHI_OFF + rb);
            ldsm_x4(bl + j * 4, st + BLO_OFF + rb);
        }

        // ---- ks = 0: mma ----
#pragma unroll
        for (int i = 0; i < 4; i++)
#pragma unroll
            for (int jj = 0; jj < 4; jj++)
                mma16816(acc[i][jj], ah[i], bh + jj * 2);   // hi*hi
#pragma unroll
        for (int i = 0; i < 4; i++)
#pragma unroll
            for (int jj = 0; jj < 4; jj++)
                mma16816(acc[i][jj], al[i], bh + jj * 2);   // lo*hi
#pragma unroll
        for (int i = 0; i < 4; i++)
#pragma unroll
            for (int jj = 0; jj < 4; jj++)
                mma16816(acc[i][jj], ah[i], bl + jj * 2);   // hi*lo

        // ---- ks = 1: ldsm ----
#pragma unroll
        for (int i = 0; i < 4; i++) {
            uint32_t rb = swz((uint32_t)(a_row + i * 16), (uint32_t)(2 + a_ch));
            ldsm_x4(ah[i], st + AHI_OFF + rb);
            ldsm_x4(al[i], st + ALO_OFF + rb);
        }
#pragma unroll
        for (int j = 0; j < 2; j++) {
            uint32_t rb = swz((uint32_t)(b_row + j * 16), (uint32_t)(2 + b_ch));
            ldsm_x4(bh + j * 4, st + BHI_OFF + rb);
            ldsm_x4(bl + j * 4, st + BLO_OFF + rb);
        }
        // smem reads of this stage all retired (data in regs): release early
        __syncwarp();
        if (lid == 0) MBARRIER_ARRIVE(sb + MB_EMPTY + cs * 8);

        // ---- ks = 1: mma ----
#pragma unroll
        for (int i = 0; i < 4; i++)
#pragma unroll
            for (int jj = 0; jj < 4; jj++)
                mma16816(acc[i][jj], ah[i], bh + jj * 2);   // hi*hi
#pragma unroll
        for (int i = 0; i < 4; i++)
#pragma unroll
            for (int jj = 0; jj < 4; jj++)
                mma16816(acc[i][jj], al[i], bh + jj * 2);   // lo*hi
#pragma unroll
        for (int i = 0; i < 4; i++)
#pragma unroll
            for (int jj = 0; jj < 4; jj++)
                mma16816(acc[i][jj], ah[i], bl + jj * 2);   // hi*lo

        // produce: prefetch kt+2 (R11 position; empty-wait usually pre-cleared
        // thanks to the early release above)
        const int nk = kt + 2;
        if (nk < KT_TILES) {
            const int ps = nk % NSTAGE;
            if (nk >= NSTAGE)
                MBARRIER_WAIT_PARITY(sb + MB_EMPTY + ps * 8,
                                     (uint32_t)(((nk / NSTAGE) - 1) & 1));
            load_stage(ps, nk);
        }
    }

    // epilogue: store C + fused row-max atomics (per-warp independent)
    const int erow = bm + warp_m * 64 + (lid >> 2);
    const int ecol = bn + warp_n * 32 + (lid & 3) * 2;
#pragma unroll
    for (int i = 0; i < 4; i++) {
#pragma unroll
        for (int half = 0; half < 2; half++) {
            float m = -3.402823466e+38f;
#pragma unroll
            for (int jj = 0; jj < 4; jj++) {
                float v0 = acc[i][jj][half * 2 + 0];
                float v1 = acc[i][jj][half * 2 + 1];
                float* p = C + (size_t)(erow + i * 16 + half * 8) * N_DIM + ecol + jj * 8;
                *reinterpret_cast<float2*>(p) = make_float2(v0, v1);
                m = fmaxf(m, fmaxf(v0, v1));
            }
            m = fmaxf(m, __shfl_xor_sync(0xffffffffu, m, 1));
            m = fmaxf(m, __shfl_xor_sync(0xffffffffu, m, 2));
            if ((lid & 3) == 0)
                atomicMax(&rmax[erow + i * 16 + half * 8], f2ord(m));
        }
    }
}

// ---------------------------------------------------------------------------
// gelu epilogue
// ---------------------------------------------------------------------------
__device__ __forceinline__ float gelu_tanh(float x) {
    const float c0 = 0.7978845608028654f;
    const float c1 = 0.044715f;
    float inner = c0 * fmaf(c1 * x, x * x, x);
    return 0.5f * x * (1.0f + tanhf(inner));
}

__global__ __launch_bounds__(256)
void gelu_kernel(const float* __restrict__ C, const unsigned* __restrict__ rmax,
                 float* __restrict__ out) {
    const size_t base = (size_t)blockIdx.x * 4096;
    const int row = (int)(base / N_DIM);
    const float mx = ord2f(rmax[row]);
    const float4* c4 = reinterpret_cast<const float4*>(C + base);
    float4* o4 = reinterpret_cast<float4*>(out + base);
    const int tid = threadIdx.x;
#pragma unroll
    for (int it = 0; it < 4; it++) {
        float4 v = c4[tid + it * 256];
        float4 r;
        r.x = gelu_tanh(v.x - mx);
        r.y = gelu_tanh(v.y - mx);
        r.z = gelu_tanh(v.z - mx);
        r.w = gelu_tanh(v.w - mx);
        o4[tid + it * 256] = r;
    }
}

// ---------------------------------------------------------------------------
extern "C" void kernel_launch(void* const* d_in, const int* in_sizes, int n_in,
                              void* d_out, int out_size) {
    const float* x = (const float*)d_in[0];   // [M, K]
    const float* w = (const float*)d_in[1];   // [N, K]
    float* out = (float*)d_out;               // [M, N]

    void *a2, *b2, *scratch, *rowmax;
    cudaGetSymbolAddress(&a2, g_A2);
    cudaGetSymbolAddress(&b2, g_B2);
    cudaGetSymbolAddress(&scratch, g_scratch);
    cudaGetSymbolAddress(&rowmax, g_rowmax_u);

    prep_kernel<<<NA_BLOCKS + NB_BLOCKS, 256>>>(
        x, w, (__nv_bfloat16*)a2, (__nv_bfloat16*)b2, (unsigned*)rowmax);

    cudaFuncSetAttribute(hgemm_kernel, cudaFuncAttributeMaxDynamicSharedMemorySize, SMEM_TOTAL);
    hgemm_kernel<<<(M_DIM / BM) * (N_DIM / BN), NTHREADS, SMEM_TOTAL>>>(
        (const __nv_bfloat16*)a2, (const __nv_bfloat16*)b2,
        (float*)scratch, (unsigned*)rowmax);

    gelu_kernel<<<(size_t)M_DIM * N_DIM / 4096, 256>>>(
        (float*)scratch, (unsigned*)rowmax, out);
}

// round 14
// speedup vs baseline: 1.0936x; 1.0046x over previous
#include <cuda_runtime.h>
#include <cuda_bf16.h>
#include <cstdint>

#define M_DIM 4096
#define N_DIM 8192
#define K_DIM 2048
#define K2    4096            // [hi | lo] along K

// GEMM tiling: 8 warps, 2(m) x 4(n), warp tile 64x32, 2 CTAs/SM
#define BM 128
#define BN 128
#define BK 32
#define NSTAGE 3
#define KT_TILES (K_DIM / BK)   // 64
#define NTHREADS 256
#define NWARPS 8

// smem: mbarriers at [0,48), tiles from 1024; 64B rows w/ XOR swizzle
#define ROW64     64
#define MB_FULL   0           // full[s] = 0 + s*8
#define MB_EMPTY  24          // empty[s] = 24 + s*8
#define SM_TILE   1024
#define AHI_OFF   0
#define ALO_OFF   8192
#define BHI_OFF   16384
#define BLO_OFF   24576
#define STAGE_B   32768
#define SMEM_TOTAL (SM_TILE + NSTAGE * STAGE_B)   // 99328/CTA (2 CTAs/SM)

// ---------------------------------------------------------------------------
// device scratch (allocation-free)
// ---------------------------------------------------------------------------
__device__ __nv_bfloat16 g_A2[(size_t)M_DIM * K2];   // [M, 2K]: hi | lo
__device__ __nv_bfloat16 g_B2[(size_t)N_DIM * K2];   // [N, 2K]: hi | lo
__device__ float g_scratch[(size_t)M_DIM * N_DIM];
__device__ unsigned g_rowmax_u[M_DIM];

// ---------------------------------------------------------------------------
// helpers
// ---------------------------------------------------------------------------
__device__ __forceinline__ uint32_t smem_u32(const void* p) {
    uint32_t a;
    asm("{ .reg .u64 t; cvta.to.shared.u64 t, %1; cvt.u32.u64 %0, t; }" : "=r"(a) : "l"(p));
    return a;
}

#define CP_ASYNC16(smem_addr, gptr) \
    asm volatile("cp.async.cg.shared.global [%0], [%1], 16;" :: "r"(smem_addr), "l"(gptr))

#define MBARRIER_INIT(addr, cnt) \
    asm volatile("mbarrier.init.shared.b64 [%0], %1;" :: "r"((uint32_t)(addr)), "r"((uint32_t)(cnt)) : "memory")
#define MBARRIER_ARRIVE(addr) \
    asm volatile("mbarrier.arrive.shared.b64 _, [%0];" :: "r"((uint32_t)(addr)) : "memory")
// .noinc is load-bearing: arrivals count against the init() count instead of
// first incrementing the pending count (which deadlocks a fixed-count barrier).
#define CP_ASYNC_MBAR_ARRIVE(addr) \
    asm volatile("cp.async.mbarrier.arrive.noinc.shared::cta.b64 [%0];" :: "r"((uint32_t)(addr)) : "memory")

#define MBARRIER_WAIT_PARITY(mbar_smem_addr, phase_parity) do { \
    uint32_t _mbar = (uint32_t)(mbar_smem_addr); \
    uint32_t _parity = (uint32_t)(phase_parity); \
    uint32_t _done; \
    asm volatile( \
        "{\n\t.reg .pred p;\n\t" \
        "mbarrier.try_wait.parity.acquire.cta.shared::cta.b64 p, [%1], %2;\n\t" \
        "selp.b32 %0, 1, 0, p;\n\t}" \
        : "=r"(_done) : "r"(_mbar), "r"(_parity) : "memory"); \
    if (!_done) { \
        asm volatile( \
            "{\n\t.reg .pred P1;\n\t" \
            "WAIT_LOOP_%=:\n\t" \
            "mbarrier.try_wait.parity.acquire.cta.shared::cta.b64 P1, [%0], %1, 0x989680;\n\t" \
            "@P1 bra.uni WAIT_DONE_%=;\n\t" \
            "bra.uni WAIT_LOOP_%=;\n\t" \
            "WAIT_DONE_%=:\n\t}" \
            :: "r"(_mbar), "r"(_parity) : "memory"); \
    } \
} while(0)

__device__ __forceinline__ void ldsm_x4(uint32_t* r, uint32_t addr) {
    asm volatile("ldmatrix.sync.aligned.m8n8.x4.shared.b16 {%0,%1,%2,%3}, [%4];"
                 : "=r"(r[0]), "=r"(r[1]), "=r"(r[2]), "=r"(r[3]) : "r"(addr));
}

__device__ __forceinline__ void mma16816(float* d, const uint32_t* a, const uint32_t* b) {
    asm volatile(
        "mma.sync.aligned.m16n8k16.row.col.f32.bf16.bf16.f32 "
        "{%0,%1,%2,%3}, {%4,%5,%6,%7}, {%8,%9}, {%0,%1,%2,%3};"
        : "+f"(d[0]), "+f"(d[1]), "+f"(d[2]), "+f"(d[3])
        : "r"(a[0]), "r"(a[1]), "r"(a[2]), "r"(a[3]), "r"(b[0]), "r"(b[1]));
}

// swizzled smem byte offset for 16B chunk c of row r (64B rows)
__device__ __forceinline__ uint32_t swz(uint32_t row, uint32_t c) {
    return row * ROW64 + ((c ^ ((row >> 1) & 3)) << 4);
}

// order-preserving float<->uint for atomicMax-based rowmax
__device__ __forceinline__ unsigned f2ord(float x) {
    unsigned u = __float_as_uint(x);
    return (u & 0x80000000u) ? ~u : (u | 0x80000000u);
}
__device__ __forceinline__ float ord2f(unsigned u) {
    u = (u & 0x80000000u) ? (u ^ 0x80000000u) : ~u;
    return __uint_as_float(u);
}

// ---------------------------------------------------------------------------
// fused prep: split x and w to bf16 [hi|lo] (8 floats/thread, 16B stores),
// init rowmax
// ---------------------------------------------------------------------------
#define NA8_BLOCKS ((M_DIM * (K_DIM / 8)) / 256)   // 4096
#define NB8_BLOCKS ((N_DIM * (K_DIM / 8)) / 256)   // 8192

__global__ __launch_bounds__(256)
void prep_kernel(const float* __restrict__ x, const float* __restrict__ w,
                 __nv_bfloat16* __restrict__ a2, __nv_bfloat16* __restrict__ b2,
                 unsigned* __restrict__ rmax) {
    const int bid = blockIdx.x;
    const float* src = (bid < NA8_BLOCKS) ? x : w;
    __nv_bfloat16* dst = (bid < NA8_BLOCKS) ? a2 : b2;
    const size_t i8 = (size_t)(bid < NA8_BLOCKS ? bid : bid - NA8_BLOCKS) * 256 + threadIdx.x;

    if (bid < 16) {   // 16*256 = 4096 rowmax entries
        rmax[bid * 256 + threadIdx.x] = 0u;
    }

    float4 v0 = reinterpret_cast<const float4*>(src)[i8 * 2];
    float4 v1 = reinterpret_cast<const float4*>(src)[i8 * 2 + 1];
    size_t r  = i8 >> 8;            // / (2048/8)
    size_t k8 = (i8 & 255) * 8;

    float f[8] = {v0.x, v0.y, v0.z, v0.w, v1.x, v1.y, v1.z, v1.w};
    uint32_t hp[4], lp[4];
#pragma unroll
    for (int j = 0; j < 4; j++) {
        __nv_bfloat16 h0 = __float2bfloat16(f[j * 2]);
        __nv_bfloat16 h1 = __float2bfloat16(f[j * 2 + 1]);
        __nv_bfloat16 l0 = __float2bfloat16(f[j * 2] - __bfloat162float(h0));
        __nv_bfloat16 l1 = __float2bfloat16(f[j * 2 + 1] - __bfloat162float(h1));
        __nv_bfloat162 hh{h0, h1}, ll{l0, l1};
        hp[j] = *reinterpret_cast<uint32_t*>(&hh);
        lp[j] = *reinterpret_cast<uint32_t*>(&ll);
    }
    uint4 hv = make_uint4(hp[0], hp[1], hp[2], hp[3]);
    uint4 lv = make_uint4(lp[0], lp[1], lp[2], lp[3]);
    *reinterpret_cast<uint4*>(dst + r * K2 + k8)         = hv;
    *reinterpret_cast<uint4*>(dst + r * K2 + K_DIM + k8) = lv;
}

// ---------------------------------------------------------------------------
// bf16 split-GEMM via mma.sync, mbarrier self-paced pipeline, early stage
// release, 2 CTAs/SM, fused rowmax  (unchanged from R13)
// C[M,N] = Ahi*Bhi^T + Alo*Bhi^T + Ahi*Blo^T
// ---------------------------------------------------------------------------
__global__ __launch_bounds__(NTHREADS, 2)
void hgemm_kernel(const __nv_bfloat16* __restrict__ A,
                  const __nv_bfloat16* __restrict__ B,
                  float* __restrict__ C,
                  unsigned* __restrict__ rmax) {
    extern __shared__ __align__(128) char smem[];
    const uint32_t sb = smem_u32(smem);
    const int tid = threadIdx.x;
    const int wid = tid >> 5;
    const int lid = tid & 31;
    const int warp_m = wid & 1;      // 2 warps along M (64 rows each)
    const int warp_n = wid >> 1;     // 4 warps along N (32 cols each)

    // grouped raster: 32 m-tiles x 64 n-tiles, GROUP_M = 8
    const int num_n = N_DIM / BN;                 // 64
    const int pid = blockIdx.x;
    const int grp = pid / (8 * num_n);
    const int pm = grp * 8 + (pid & 7);
    const int pn = (pid % (8 * num_n)) >> 3;
    const int bm = pm * BM;
    const int bn = pn * BN;

    // mbarrier init
    if (tid == 0) {
#pragma unroll
        for (int s = 0; s < NSTAGE; s++) {
            MBARRIER_INIT(sb + MB_FULL + s * 8, NTHREADS);
            MBARRIER_INIT(sb + MB_EMPTY + s * 8, NWARPS);
        }
    }
    __syncthreads();

    // gmem load mapping: 256 threads; row = tid>>1 (0..127), 2 chunks each
    const int r0 = tid >> 1;
    const int cp0 = (tid & 1) * 2;   // chunks cp0, cp0+1
    const __nv_bfloat16* gA = A + (size_t)(bm + r0) * K2 + cp0 * 8;
    const __nv_bfloat16* gB = B + (size_t)(bn + r0) * K2 + cp0 * 8;
    const uint32_t d0 = swz((uint32_t)r0, (uint32_t)cp0);
    const uint32_t d1 = swz((uint32_t)r0, (uint32_t)cp0 + 1);

    auto load_stage = [&](int s, int kt) {
        uint32_t st = sb + SM_TILE + s * STAGE_B;
        const int kc = kt * BK;
        const __nv_bfloat16* a = gA + kc;
        const __nv_bfloat16* b = gB + kc;
        CP_ASYNC16(st + AHI_OFF + d0, a);
        CP_ASYNC16(st + AHI_OFF + d1, a + 8);
        CP_ASYNC16(st + ALO_OFF + d0, a + K_DIM);
        CP_ASYNC16(st + ALO_OFF + d1, a + K_DIM + 8);
        CP_ASYNC16(st + BHI_OFF + d0, b);
        CP_ASYNC16(st + BHI_OFF + d1, b + 8);
        CP_ASYNC16(st + BLO_OFF + d0, b + K_DIM);
        CP_ASYNC16(st + BLO_OFF + d1, b + K_DIM + 8);
        CP_ASYNC_MBAR_ARRIVE(sb + MB_FULL + s * 8);
    };

    float acc[4][4][4];
#pragma unroll
    for (int i = 0; i < 4; i++)
#pragma unroll
        for (int j = 0; j < 4; j++)
#pragma unroll
            for (int q = 0; q < 4; q++)
                acc[i][j][q] = 0.0f;

    // prologue: fill stages 0 and 1 (no empty-wait on first use)
    load_stage(0, 0);
    load_stage(1, 1);

    // ldmatrix lane addressing (row + chunk index per lane)
    const int a_row = warp_m * 64 + (lid & 15);                         // + i*16
    const int a_ch  = (lid >> 4);                                       // + ks*2
    const int b_row = warp_n * 32 + (lid & 7) + ((lid >> 4) & 1) * 8;   // + j*16
    const int b_ch  = ((lid >> 3) & 1);                                 // + ks*2

    for (int kt = 0; kt < KT_TILES; kt++) {
        const int cs = kt % NSTAGE;
        // consume: wait stage full (parity = (kt/3)&1)
        MBARRIER_WAIT_PARITY(sb + MB_FULL + cs * 8, (uint32_t)((kt / NSTAGE) & 1));

        const uint32_t st = sb + SM_TILE + cs * STAGE_B;
        uint32_t ah[4][4], al[4][4], bh[8], bl[8];

        // ---- ks = 0: ldsm ----
#pragma unroll
        for (int i = 0; i < 4; i++) {
            uint32_t rb = swz((uint32_t)(a_row + i * 16), (uint32_t)a_ch);
            ldsm_x4(ah[i], st + AHI_OFF + rb);
            ldsm_x4(al[i], st + ALO_OFF + rb);
        }
#pragma unroll
        for (int j = 0; j < 2; j++) {
            uint32_t rb = swz((uint32_t)(b_row + j * 16), (uint32_t)b_ch);
            ldsm_x4(bh + j * 4, st + BHI_OFF + rb);
            ldsm_x4(bl + j * 4, st + BLO_OFF + rb);
        }

        // ---- ks = 0: mma ----
#pragma unroll
        for (int i = 0; i < 4; i++)
#pragma unroll
            for (int jj = 0; jj < 4; jj++)
                mma16816(acc[i][jj], ah[i], bh + jj * 2);   // hi*hi
#pragma unroll
        for (int i = 0; i < 4; i++)
#pragma unroll
            for (int jj = 0; jj < 4; jj++)
                mma16816(acc[i][jj], al[i], bh + jj * 2);   // lo*hi
#pragma unroll
        for (int i = 0; i < 4; i++)
#pragma unroll
            for (int jj = 0; jj < 4; jj++)
                mma16816(acc[i][jj], ah[i], bl + jj * 2);   // hi*lo

        // ---- ks = 1: ldsm ----
#pragma unroll
        for (int i = 0; i < 4; i++) {
            uint32_t rb = swz((uint32_t)(a_row + i * 16), (uint32_t)(2 + a_ch));
            ldsm_x4(ah[i], st + AHI_OFF + rb);
            ldsm_x4(al[i], st + ALO_OFF + rb);
        }
#pragma unroll
        for (int j = 0; j < 2; j++) {
            uint32_t rb = swz((uint32_t)(b_row + j * 16), (uint32_t)(2 + b_ch));
            ldsm_x4(bh + j * 4, st + BHI_OFF + rb);
            ldsm_x4(bl + j * 4, st + BLO_OFF + rb);
        }
        // smem reads of this stage all retired (data in regs): release early
        __syncwarp();
        if (lid == 0) MBARRIER_ARRIVE(sb + MB_EMPTY + cs * 8);

        // ---- ks = 1: mma ----
#pragma unroll
        for (int i = 0; i < 4; i++)
#pragma unroll
            for (int jj = 0; jj < 4; jj++)
                mma16816(acc[i][jj], ah[i], bh + jj * 2);   // hi*hi
#pragma unroll
        for (int i = 0; i < 4; i++)
#pragma unroll
            for (int jj = 0; jj < 4; jj++)
                mma16816(acc[i][jj], al[i], bh + jj * 2);   // lo*hi
#pragma unroll
        for (int i = 0; i < 4; i++)
#pragma unroll
            for (int jj = 0; jj < 4; jj++)
                mma16816(acc[i][jj], ah[i], bl + jj * 2);   // hi*lo

        // produce: prefetch kt+2 (empty-wait usually pre-cleared by the
        // early release above)
        const int nk = kt + 2;
        if (nk < KT_TILES) {
            const int ps = nk % NSTAGE;
            if (nk >= NSTAGE)
                MBARRIER_WAIT_PARITY(sb + MB_EMPTY + ps * 8,
                                     (uint32_t)(((nk / NSTAGE) - 1) & 1));
            load_stage(ps, nk);
        }
    }

    // epilogue: store C + fused row-max atomics (per-warp independent)
    const int erow = bm + warp_m * 64 + (lid >> 2);
    const int ecol = bn + warp_n * 32 + (lid & 3) * 2;
#pragma unroll
    for (int i = 0; i < 4; i++) {
#pragma unroll
        for (int half = 0; half < 2; half++) {
            float m = -3.402823466e+38f;
#pragma unroll
            for (int jj = 0; jj < 4; jj++) {
                float v0 = acc[i][jj][half * 2 + 0];
                float v1 = acc[i][jj][half * 2 + 1];
                float* p = C + (size_t)(erow + i * 16 + half * 8) * N_DIM + ecol + jj * 8;
                *reinterpret_cast<float2*>(p) = make_float2(v0, v1);
                m = fmaxf(m, fmaxf(v0, v1));
            }
            m = fmaxf(m, __shfl_xor_sync(0xffffffffu, m, 1));
            m = fmaxf(m, __shfl_xor_sync(0xffffffffu, m, 2));
            if ((lid & 3) == 0)
                atomicMax(&rmax[erow + i * 16 + half * 8], f2ord(m));
        }
    }
}

// ---------------------------------------------------------------------------
// gelu epilogue: one block per row, 8 float4 per thread (high MLP)
// ---------------------------------------------------------------------------
__device__ __forceinline__ float gelu_tanh(float x) {
    const float c0 = 0.7978845608028654f;
    const float c1 = 0.044715f;
    float inner = c0 * fmaf(c1 * x, x * x, x);
    return 0.5f * x * (1.0f + tanhf(inner));
}

__global__ __launch_bounds__(256)
void gelu_kernel(const float* __restrict__ C, const unsigned* __restrict__ rmax,
                 float* __restrict__ out) {
    const int row = blockIdx.x;
    const float mx = ord2f(rmax[row]);
    const float4* c4 = reinterpret_cast<const float4*>(C + (size_t)row * N_DIM);
    float4* o4 = reinterpret_cast<float4*>(out + (size_t)row * N_DIM);
    const int tid = threadIdx.x;

    float4 v[8];
#pragma unroll
    for (int it = 0; it < 8; it++)
        v[it] = c4[tid + it * 256];
#pragma unroll
    for (int it = 0; it < 8; it++) {
        float4 r;
        r.x = gelu_tanh(v[it].x - mx);
        r.y = gelu_tanh(v[it].y - mx);
        r.z = gelu_tanh(v[it].z - mx);
        r.w = gelu_tanh(v[it].w - mx);
        o4[tid + it * 256] = r;
    }
}

// ---------------------------------------------------------------------------
extern "C" void kernel_launch(void* const* d_in, const int* in_sizes, int n_in,
                              void* d_out, int out_size) {
    const float* x = (const float*)d_in[0];   // [M, K]
    const float* w = (const float*)d_in[1];   // [N, K]
    float* out = (float*)d_out;               // [M, N]

    void *a2, *b2, *scratch, *rowmax;
    cudaGetSymbolAddress(&a2, g_A2);
    cudaGetSymbolAddress(&b2, g_B2);
    cudaGetSymbolAddress(&scratch, g_scratch);
    cudaGetSymbolAddress(&rowmax, g_rowmax_u);

    prep_kernel<<<NA8_BLOCKS + NB8_BLOCKS, 256>>>(
        x, w, (__nv_bfloat16*)a2, (__nv_bfloat16*)b2, (unsigned*)rowmax);

    cudaFuncSetAttribute(hgemm_kernel, cudaFuncAttributeMaxDynamicSharedMemorySize, SMEM_TOTAL);
    hgemm_kernel<<<(M_DIM / BM) * (N_DIM / BN), NTHREADS, SMEM_TOTAL>>>(
        (const __nv_bfloat16*)a2, (const __nv_bfloat16*)b2,
        (float*)scratch, (unsigned*)rowmax);

    gelu_kernel<<<M_DIM, 256>>>((float*)scratch, (unsigned*)rowmax, out);
}